// round 14
// baseline (speedup 1.0000x reference)
#include <cuda_runtime.h>
#include <cuda_fp16.h>
#include <cstdint>
#include <cfloat>

// Quantize_8881992368326 — VQ-VAE eval forward.
// R13 base (score-in-MMA folding, TPB=512, TILE_M=256, fused finalize)
// + software-pipelined mainloop: 32-code sub-chunks, double-buffered accumulators,
//   MMA(s+1) issued before epilogue(s) so tensor/LDS latency overlaps ALU chain.
// Exact fp32 fallback with TRUE per-chunk-max pruning.
// x: [131072, 64] f32, embed: [64, 512] f32 (dim-major).
// out (f32): quantize[131072*64] | diff[1] | embed_ind[131072]

#define DIM     64
#define NE      512
#define NROWS   (32*64*64)
#define TILE_M  256
#define NTILES  (NROWS / TILE_M)   /* 512 */
#define GRIDSZ  148
#define TPB     512
#define NWARP   (TPB/32)
#define MARGIN  0.6f
#define BIAS    2048.0f
#define CBS     68                 /* fp32 codebook row stride (floats), pad for banks */

// SMEM layout (bytes)
#define OFF_B      0                         /* f16 B (=2*e): 512 codes x 128B, swizzled */
#define OFF_NORMB  65536                     /* 512 f32: BIAS - ||e||^2 */
#define OFF_NORM   67584                     /* 512 f32: exact ||e||^2 */
#define OFF_CB     69632                     /* fp32 codebook 512 x CBS */
#define OFF_SCMAX  (OFF_CB + NE*CBS*4)       /* 256 rows x 8 chunk-max f32 */
#define OFF_WIDX   (OFF_SCMAX + TILE_M*8*4)  /* 256 int */
#define OFF_RED    (OFF_WIDX + TILE_M*4)     /* 16 f32 */
#define SMEM_TOTAL (OFF_RED + NWARP*4)       /* ~218 KB */

__device__ float g_partials[GRIDSZ];
__device__ unsigned int g_done;              // zero-init; reset by last block each launch

__device__ __forceinline__ uint32_t f2h2(float lo, float hi) {
    uint32_t r;
    asm("cvt.rn.f16x2.f32 %0, %1, %2;" : "=r"(r) : "f"(hi), "f"(lo)); // %1 -> upper half
    return r;
}
__device__ __forceinline__ void mma_f16(float& c0, float& c1, float& c2, float& c3,
                                        uint32_t a0, uint32_t a1, uint32_t a2, uint32_t a3,
                                        uint32_t b0, uint32_t b1) {
    asm volatile("mma.sync.aligned.m16n8k16.row.col.f32.f16.f16.f32 "
                 "{%0,%1,%2,%3}, {%4,%5,%6,%7}, {%8,%9}, {%0,%1,%2,%3};"
                 : "+f"(c0), "+f"(c1), "+f"(c2), "+f"(c3)
                 : "r"(a0), "r"(a1), "r"(a2), "r"(a3), "r"(b0), "r"(b1));
}
// biased-positive score -> sortable key (single LOP3); idxc = 511 - j in low 9 bits
__device__ __forceinline__ uint32_t skey(float s, uint32_t idxc) {
    return (__float_as_uint(s) & 0xfffffe00u) | idxc;
}
__device__ __forceinline__ float keyf_s(uint32_t k) {    // decode to unbiased s-space
    return __uint_as_float(k & 0xfffffe00u) - BIAS;
}
__device__ __forceinline__ void upd(uint32_t& m1, uint32_t& m2, uint32_t& cm, uint32_t k) {
    cm = max(cm, k);
    m2 = max(m2, min(m1, k));
    m1 = max(m1, k);
}

__global__ __launch_bounds__(TPB, 1)
void vq_kernel(const float* __restrict__ x,
               const float* __restrict__ embed,
               float* __restrict__ out_q,
               float* __restrict__ out_idx,
               float* __restrict__ out_diff)
{
    extern __shared__ char smem[];
    float* cbf    = (float*)(smem + OFF_CB);
    float* snormb = (float*)(smem + OFF_NORMB);
    float* snorm  = (float*)(smem + OFF_NORM);
    float* scmaxf = (float*)(smem + OFF_SCMAX);
    int*   swidx  = (int*)(smem + OFF_WIDX);
    float* sred   = (float*)(smem + OFF_RED);

    const int tid  = threadIdx.x;
    const int lane = tid & 31;
    const int wid  = tid >> 5;
    const int gid  = lane >> 2;   // 0..7
    const int tig  = lane & 3;    // 0..3

    // ---- build smem: fp32 codebook (transposed), norms, f16 B = 2*e (swizzled) ----
    for (int i = tid; i < DIM * NE; i += TPB) {       // coalesced read of embed
        int k = i >> 9, j = i & 511;
        cbf[j * CBS + k] = embed[i];
    }
    __syncthreads();
    for (int j = tid; j < NE; j += TPB) {
        const float* e = cbf + j * CBS;
        float n = 0.f;
        #pragma unroll
        for (int k = 0; k < DIM; k++) n = fmaf(e[k], e[k], n);
        snorm[j]  = n;
        snormb[j] = BIAS - n;
    }
    for (int i = tid; i < NE * 32; i += TPB) {        // 32 f16x2 pairs per code (2*e)
        int j = i >> 5, p = i & 31;
        int blk = p >> 3, s = p & 7;
        int P = (s >> 1) + ((s & 1) << 2);            // pair index within k16 block
        int k = blk * 16 + P * 2;
        uint32_t h2 = f2h2(2.f * cbf[j * CBS + k], 2.f * cbf[j * CBS + k + 1]);
        uint32_t off = (uint32_t)(j * 128) + (((uint32_t)(blk * 32 + s * 4)) ^ (((uint32_t)(j & 3)) << 5));
        *(uint32_t*)(smem + OFF_B + off) = h2;
    }
    __syncthreads();

    const uint32_t bsw = ((uint32_t)(gid & 3)) << 5;  // (j&3)<<5 is constant per thread
    float blockdiff = 0.f;

    for (int t = blockIdx.x; t < NTILES; t += GRIDSZ) {
        const int rowbase = t * TILE_M + wid * 16;

        // ---- A fragments: rows gid & gid+8, k16 x 4 steps
        uint32_t a[4][4];
        {
            const float* xr0 = x + (size_t)(rowbase + gid) * DIM;
            const float* xr8 = xr0 + 8 * DIM;
            #pragma unroll
            for (int ks = 0; ks < 4; ks++) {
                float2 p;
                p = *(const float2*)(xr0 + ks * 16 + 2 * tig);     a[ks][0] = f2h2(p.x, p.y);
                p = *(const float2*)(xr8 + ks * 16 + 2 * tig);     a[ks][1] = f2h2(p.x, p.y);
                p = *(const float2*)(xr0 + ks * 16 + 2 * tig + 8); a[ks][2] = f2h2(p.x, p.y);
                p = *(const float2*)(xr8 + ks * 16 + 2 * tig + 8); a[ks][3] = f2h2(p.x, p.y);
            }
        }

        uint32_t m1[2] = {0u, 0u}, m2[2] = {0u, 0u};
        uint32_t cm[2] = {0u, 0u};

        // issue MMA stream for 32-code sub-chunk s into acc (init = BIAS - ||e||^2)
        auto mma_sub = [&](int s, float (&acc)[4][4]) {
            const int jb = s * 32 + 2 * tig;
            #pragma unroll
            for (int nt = 0; nt < 4; nt++) {
                float2 nb = *(const float2*)(snormb + jb + nt * 8);
                acc[nt][0] = nb.x; acc[nt][1] = nb.y;
                acc[nt][2] = nb.x; acc[nt][3] = nb.y;
            }
            const int jrow0 = s * 32 + gid;
            #pragma unroll
            for (int ks = 0; ks < 4; ks++) {
                #pragma unroll
                for (int nt = 0; nt < 4; nt++) {
                    uint32_t off = (uint32_t)((jrow0 + nt * 8) * 128) +
                                   (((uint32_t)(ks * 32 + tig * 8)) ^ bsw);
                    uint2 b = *(const uint2*)(smem + OFF_B + off);
                    mma_f16(acc[nt][0], acc[nt][1], acc[nt][2], acc[nt][3],
                            a[ks][0], a[ks][1], a[ks][2], a[ks][3], b.x, b.y);
                }
            }
        };
        // epilogue for sub-chunk s; wr=true -> second half of a 64-code chunk:
        // quad-reduce TRUE chunk max, write scmax, reset cm
        auto epi_sub = [&](int s, float (&acc)[4][4], bool wr) {
            const int jb = s * 32 + 2 * tig;
            #pragma unroll
            for (int nt = 0; nt < 4; nt++) {
                uint32_t ic0 = (uint32_t)(511 - (jb + nt * 8));
                uint32_t ic1 = ic0 - 1;
                upd(m1[0], m2[0], cm[0], skey(acc[nt][0], ic0));
                upd(m1[0], m2[0], cm[0], skey(acc[nt][1], ic1));
                upd(m1[1], m2[1], cm[1], skey(acc[nt][2], ic0));
                upd(m1[1], m2[1], cm[1], skey(acc[nt][3], ic1));
            }
            if (wr) {
                #pragma unroll
                for (int h = 0; h < 2; h++) {
                    uint32_t v = cm[h];
                    v = max(v, __shfl_xor_sync(0xffffffffu, v, 1));
                    v = max(v, __shfl_xor_sync(0xffffffffu, v, 2));
                    if (tig == 0) scmaxf[(wid * 16 + h * 8 + gid) * 8 + (s >> 1)] = keyf_s(v);
                    cm[h] = 0u;
                }
            }
        };

        // ---- software-pipelined mainloop: MMA(s+1) issues before epilogue(s)
        float accA[4][4], accB[4][4];
        mma_sub(0, accA);
        #pragma unroll 1
        for (int s = 0; s < 16; s += 2) {
            mma_sub(s + 1, accB);          // overlaps epi(s) below
            epi_sub(s, accA, false);
            if (s + 2 < 16) mma_sub(s + 2, accA);   // overlaps epi(s+1)
            epi_sub(s + 1, accB, true);
        }

        // ---- quad merge of (m1, m2)
        #pragma unroll
        for (int h = 0; h < 2; h++) {
            #pragma unroll
            for (int off = 1; off <= 2; off <<= 1) {
                uint32_t om1 = __shfl_xor_sync(0xffffffffu, m1[h], off);
                uint32_t om2 = __shfl_xor_sync(0xffffffffu, m2[h], off);
                uint32_t lo = min(m1[h], om1);
                m1[h] = max(m1[h], om1);
                m2[h] = max(max(m2[h], om2), lo);
            }
        }

        int jwin[2]; float bestf[2], gapf[2];
        #pragma unroll
        for (int h = 0; h < 2; h++) {
            jwin[h]  = 511 - (int)(m1[h] & 511u);
            bestf[h] = keyf_s(m1[h]);
            gapf[h]  = bestf[h] - keyf_s(m2[h]);
        }

        __syncwarp();

        // ---- exact fp32 fallback for ambiguous rows (warp-cooperative, rare)
        #pragma unroll 1
        for (int h = 0; h < 2; h++) {
            unsigned mask = __ballot_sync(0xffffffffu, (tig == 0) && (gapf[h] < MARGIN));
            while (mask) {
                int l = __ffs(mask) - 1; mask &= mask - 1;
                int g = l >> 2;
                int lrow = wid * 16 + h * 8 + g;
                float thr = __shfl_sync(0xffffffffu, bestf[h], l) - MARGIN;
                const float4* xr4 = (const float4*)(x + (size_t)(t * TILE_M + lrow) * DIM);

                float bw = -FLT_MAX; int wj = NE;
                for (int ch = 0; ch < 8; ch++) {
                    if (scmaxf[lrow * 8 + ch] < thr) continue;
                    #pragma unroll
                    for (int half = 0; half < 2; half++) {
                        int j = ch * 64 + half * 32 + lane;
                        const float4* e4 = (const float4*)(cbf + j * CBS);
                        float d0 = 0.f, d1 = 0.f, d2 = 0.f, d3 = 0.f;
                        #pragma unroll
                        for (int v = 0; v < 16; v++) {
                            float4 fv = xr4[v]; float4 ev = e4[v];
                            d0 = fmaf(fv.x, ev.x, d0); d1 = fmaf(fv.y, ev.y, d1);
                            d2 = fmaf(fv.z, ev.z, d2); d3 = fmaf(fv.w, ev.w, d3);
                        }
                        float s = fmaf(2.f, (d0 + d1) + (d2 + d3), -snorm[j]);
                        if (s > bw || (s == bw && j < wj)) { bw = s; wj = j; }
                    }
                }
                #pragma unroll
                for (int off = 16; off > 0; off >>= 1) {
                    float ob = __shfl_xor_sync(0xffffffffu, bw, off);
                    int   oj = __shfl_xor_sync(0xffffffffu, wj, off);
                    if (ob > bw || (ob == bw && oj < wj)) { bw = ob; wj = oj; }
                }
                if (lane == l) jwin[h] = wj;
            }
        }

        if (tig == 0) {
            swidx[wid * 16 + gid]     = jwin[0];
            swidx[wid * 16 + 8 + gid] = jwin[1];
        }
        __syncthreads();

        // ---- output gather (from smem fp32 codebook) + exact diff
        const float4* xin = (const float4*)(x + (size_t)t * TILE_M * DIM);
        float4* oq = (float4*)(out_q + (size_t)t * TILE_M * DIM);
        const float4* cb4 = (const float4*)cbf;   // row stride CBS/4 float4
        float td = 0.f;
        #pragma unroll
        for (int it = 0; it < (TILE_M * 16) / TPB; it++) {
            int i = tid + it * TPB;
            int row = i >> 4, v = i & 15;
            float4 e = cb4[swidx[row] * (CBS / 4) + v];
            float4 xv = xin[i];
            oq[i] = e;
            float d0 = e.x - xv.x, d1 = e.y - xv.y, d2 = e.z - xv.z, d3 = e.w - xv.w;
            td = fmaf(d0, d0, td); td = fmaf(d1, d1, td);
            td = fmaf(d2, d2, td); td = fmaf(d3, d3, td);
        }
        if (tid < TILE_M) out_idx[(size_t)t * TILE_M + tid] = (float)swidx[tid];

        #pragma unroll
        for (int off = 16; off > 0; off >>= 1)
            td += __shfl_down_sync(0xffffffffu, td, off);
        if (lane == 0) sred[wid] = td;
        __syncthreads();
        if (tid == 0) {
            float s = 0.f;
            #pragma unroll
            for (int w = 0; w < NWARP; w++) s += sred[w];
            blockdiff += s;                       // fixed tile order per block
        }
        __syncthreads();
    }

    // ---- fused deterministic finalize: last block sums per-block partials
    if (tid == 0) {
        g_partials[blockIdx.x] = blockdiff;
        __threadfence();
        unsigned int prev = atomicAdd(&g_done, 1u);
        if (prev == GRIDSZ - 1) {
            float s = 0.f;
            #pragma unroll 4
            for (int i = 0; i < GRIDSZ; i++) s += g_partials[i];   // fixed order
            *out_diff = s * (1.0f / (float)((size_t)NROWS * DIM));
            g_done = 0;                           // reset for next graph replay
            __threadfence();
        }
    }
}

extern "C" void kernel_launch(void* const* d_in, const int* in_sizes, int n_in,
                              void* d_out, int out_size)
{
    const float* x     = (const float*)d_in[0];
    const float* embed = (const float*)d_in[1];

    float* out      = (float*)d_out;
    float* out_q    = out;
    float* out_diff = out + (size_t)NROWS * DIM;
    float* out_idx  = out + (size_t)NROWS * DIM + 1;

    cudaFuncSetAttribute(vq_kernel, cudaFuncAttributeMaxDynamicSharedMemorySize, SMEM_TOTAL);

    vq_kernel<<<GRIDSZ, TPB, SMEM_TOTAL>>>(x, embed, out_q, out_idx, out_diff);
}

// round 15
// speedup vs baseline: 1.0316x; 1.0316x over previous
#include <cuda_runtime.h>
#include <cuda_fp16.h>
#include <cstdint>
#include <cfloat>

// Quantize_8881992368326 — VQ-VAE eval forward.  [FINAL — measured best: 103.4 us]
// mma.sync m16n8k16 f16 (fp32 accum) + branch-free keyed argmax + exact fp32 fallback.
// Fused deterministic diff finalize (last-block pattern). 16 warps/CTA.
// x: [131072, 64] f32, embed: [64, 512] f32 (dim-major).
// out (f32): quantize[131072*64] | diff[1] | embed_ind[131072]

#define DIM     64
#define NE      512
#define NROWS   (32*64*64)
#define TILE_M  256
#define NTILES  (NROWS / TILE_M)   /* 512 */
#define GRIDSZ  148
#define TPB     512
#define NWARP   (TPB/32)
#define MARGIN  0.4f
#define CBS     68                 /* fp32 codebook row stride (floats), pad for banks */

// SMEM layout (bytes)
#define OFF_B      0                         /* f16 B: 512 codes x 128B, swizzled */
#define OFF_NORM   65536                     /* 512 f32 */
#define OFF_CB     67584                     /* fp32 codebook 512 x CBS */
#define OFF_SCMAX  (OFF_CB + NE*CBS*4)       /* 256 rows x 8 chunk-max f32 */
#define OFF_WIDX   (OFF_SCMAX + TILE_M*8*4)  /* 256 int */
#define OFF_RED    (OFF_WIDX + TILE_M*4)     /* 16 f32 */
#define SMEM_TOTAL (OFF_RED + NWARP*4)       /* ~216 KB */

__device__ float g_partials[GRIDSZ];
__device__ unsigned int g_done;              // zero-init; reset by last block each launch

__device__ __forceinline__ uint32_t f2h2(float lo, float hi) {
    uint32_t r;
    asm("cvt.rn.f16x2.f32 %0, %1, %2;" : "=r"(r) : "f"(hi), "f"(lo)); // %1 -> upper half
    return r;
}
__device__ __forceinline__ void mma_f16(float& c0, float& c1, float& c2, float& c3,
                                        uint32_t a0, uint32_t a1, uint32_t a2, uint32_t a3,
                                        uint32_t b0, uint32_t b1) {
    asm volatile("mma.sync.aligned.m16n8k16.row.col.f32.f16.f16.f32 "
                 "{%0,%1,%2,%3}, {%4,%5,%6,%7}, {%8,%9}, {%0,%1,%2,%3};"
                 : "+f"(c0), "+f"(c1), "+f"(c2), "+f"(c3)
                 : "r"(a0), "r"(a1), "r"(a2), "r"(a3), "r"(b0), "r"(b1));
}
// float -> sortable uint, idx packed in low 9 bits (idxc = 511 - j; bigger = smaller j)
__device__ __forceinline__ uint32_t skey(float s, uint32_t idxc) {
    int i = __float_as_int(s);
    uint32_t u = (uint32_t)(i ^ ((i >> 31) | 0x80000000));
    return (u & 0xfffffe00u) | idxc;
}
__device__ __forceinline__ float keyf(uint32_t k) {
    uint32_t u = k & 0xfffffe00u;
    int i = (u & 0x80000000u) ? (int)(u ^ 0x80000000u) : ~(int)u;
    return __int_as_float(i);
}
__device__ __forceinline__ void upd(uint32_t& m1, uint32_t& m2, uint32_t& cm, uint32_t k) {
    cm = max(cm, k);
    m2 = max(m2, min(m1, k));
    m1 = max(m1, k);
}

__global__ __launch_bounds__(TPB, 1)
void vq_kernel(const float* __restrict__ x,
               const float* __restrict__ embed,
               float* __restrict__ out_q,
               float* __restrict__ out_idx,
               float* __restrict__ out_diff)
{
    extern __shared__ char smem[];
    float* cbf    = (float*)(smem + OFF_CB);
    float* snorm  = (float*)(smem + OFF_NORM);
    float* scmaxf = (float*)(smem + OFF_SCMAX);
    int*   swidx  = (int*)(smem + OFF_WIDX);
    float* sred   = (float*)(smem + OFF_RED);

    const int tid  = threadIdx.x;
    const int lane = tid & 31;
    const int wid  = tid >> 5;
    const int gid  = lane >> 2;   // 0..7
    const int tig  = lane & 3;    // 0..3

    // ---- build smem: fp32 codebook (transposed), norms, f16 B (swizzled) ----
    for (int i = tid; i < DIM * NE; i += TPB) {       // coalesced read of embed
        int k = i >> 9, j = i & 511;
        cbf[j * CBS + k] = embed[i];
    }
    __syncthreads();
    for (int j = tid; j < NE; j += TPB) {
        const float* e = cbf + j * CBS;
        float n = 0.f;
        #pragma unroll
        for (int k = 0; k < DIM; k++) n = fmaf(e[k], e[k], n);
        snorm[j] = n;
    }
    for (int i = tid; i < NE * 32; i += TPB) {        // 32 f16x2 pairs per code
        int j = i >> 5, p = i & 31;
        int blk = p >> 3, s = p & 7;
        int P = (s >> 1) + ((s & 1) << 2);            // pair index within k16 block
        int k = blk * 16 + P * 2;
        uint32_t h2 = f2h2(cbf[j * CBS + k], cbf[j * CBS + k + 1]);
        uint32_t off = (uint32_t)(j * 128) + (((uint32_t)(blk * 32 + s * 4)) ^ (((uint32_t)(j & 3)) << 5));
        *(uint32_t*)(smem + OFF_B + off) = h2;
    }
    __syncthreads();

    const uint32_t bsw = ((uint32_t)(gid & 3)) << 5;  // (j&3)<<5 is constant per thread
    float blockdiff = 0.f;

    for (int t = blockIdx.x; t < NTILES; t += GRIDSZ) {
        const int rowbase = t * TILE_M + wid * 16;

        // ---- A fragments: rows gid & gid+8, k16 x 4 steps
        uint32_t a[4][4];
        {
            const float* xr0 = x + (size_t)(rowbase + gid) * DIM;
            const float* xr8 = xr0 + 8 * DIM;
            #pragma unroll
            for (int ks = 0; ks < 4; ks++) {
                float2 p;
                p = *(const float2*)(xr0 + ks * 16 + 2 * tig);     a[ks][0] = f2h2(p.x, p.y);
                p = *(const float2*)(xr8 + ks * 16 + 2 * tig);     a[ks][1] = f2h2(p.x, p.y);
                p = *(const float2*)(xr0 + ks * 16 + 2 * tig + 8); a[ks][2] = f2h2(p.x, p.y);
                p = *(const float2*)(xr8 + ks * 16 + 2 * tig + 8); a[ks][3] = f2h2(p.x, p.y);
            }
        }

        uint32_t m1[2] = {0u, 0u}, m2[2] = {0u, 0u};

        #pragma unroll 1
        for (int chunk = 0; chunk < 8; chunk++) {
            float acc[8][4];
            #pragma unroll
            for (int nt = 0; nt < 8; nt++)
                #pragma unroll
                for (int q = 0; q < 4; q++) acc[nt][q] = 0.f;

            const int jrow0 = chunk * 64 + gid;       // this lane's B code for nt=0
            #pragma unroll
            for (int ks = 0; ks < 4; ks++) {
                #pragma unroll
                for (int nt = 0; nt < 8; nt++) {
                    uint32_t off = (uint32_t)((jrow0 + nt * 8) * 128) +
                                   (((uint32_t)(ks * 32 + tig * 8)) ^ bsw);
                    uint2 b = *(const uint2*)(smem + OFF_B + off);
                    mma_f16(acc[nt][0], acc[nt][1], acc[nt][2], acc[nt][3],
                            a[ks][0], a[ks][1], a[ks][2], a[ks][3], b.x, b.y);
                }
            }

            // ---- branch-free epilogue
            uint32_t cm[2] = {0u, 0u};
            const int jb = chunk * 64 + 2 * tig;
            #pragma unroll
            for (int nt = 0; nt < 8; nt++) {
                float2 nrm = *(const float2*)(snorm + jb + nt * 8);
                uint32_t ic0 = (uint32_t)(511 - (jb + nt * 8));
                uint32_t ic1 = ic0 - 1;
                float s;
                s = fmaf(2.f, acc[nt][0], -nrm.x); upd(m1[0], m2[0], cm[0], skey(s, ic0));
                s = fmaf(2.f, acc[nt][1], -nrm.y); upd(m1[0], m2[0], cm[0], skey(s, ic1));
                s = fmaf(2.f, acc[nt][2], -nrm.x); upd(m1[1], m2[1], cm[1], skey(s, ic0));
                s = fmaf(2.f, acc[nt][3], -nrm.y); upd(m1[1], m2[1], cm[1], skey(s, ic1));
            }
            #pragma unroll
            for (int h = 0; h < 2; h++) {
                uint32_t v = cm[h];
                v = max(v, __shfl_xor_sync(0xffffffffu, v, 1));
                v = max(v, __shfl_xor_sync(0xffffffffu, v, 2));
                if (tig == 0) scmaxf[(wid * 16 + h * 8 + gid) * 8 + chunk] = keyf(v);
            }
        }

        // ---- quad merge of (m1, m2)
        #pragma unroll
        for (int h = 0; h < 2; h++) {
            #pragma unroll
            for (int off = 1; off <= 2; off <<= 1) {
                uint32_t om1 = __shfl_xor_sync(0xffffffffu, m1[h], off);
                uint32_t om2 = __shfl_xor_sync(0xffffffffu, m2[h], off);
                uint32_t lo = min(m1[h], om1);
                m1[h] = max(m1[h], om1);
                m2[h] = max(max(m2[h], om2), lo);
            }
        }

        int jwin[2]; float bestf[2], gapf[2];
        #pragma unroll
        for (int h = 0; h < 2; h++) {
            jwin[h] = 511 - (int)(m1[h] & 511u);
            bestf[h] = keyf(m1[h]);
            gapf[h] = bestf[h] - keyf(m2[h]);
        }

        __syncwarp();

        // ---- exact fp32 fallback for ambiguous rows (warp-cooperative, rare)
        #pragma unroll 1
        for (int h = 0; h < 2; h++) {
            unsigned mask = __ballot_sync(0xffffffffu, (tig == 0) && (gapf[h] < MARGIN));
            while (mask) {
                int l = __ffs(mask) - 1; mask &= mask - 1;
                int g = l >> 2;
                int lrow = wid * 16 + h * 8 + g;
                float thr = __shfl_sync(0xffffffffu, bestf[h], l) - MARGIN;
                const float4* xr4 = (const float4*)(x + (size_t)(t * TILE_M + lrow) * DIM);

                float bw = -FLT_MAX; int wj = NE;
                for (int ch = 0; ch < 8; ch++) {
                    if (scmaxf[lrow * 8 + ch] < thr) continue;
                    #pragma unroll
                    for (int half = 0; half < 2; half++) {
                        int j = ch * 64 + half * 32 + lane;
                        const float4* e4 = (const float4*)(cbf + j * CBS);
                        float d0 = 0.f, d1 = 0.f, d2 = 0.f, d3 = 0.f;
                        #pragma unroll
                        for (int v = 0; v < 16; v++) {
                            float4 fv = xr4[v]; float4 ev = e4[v];
                            d0 = fmaf(fv.x, ev.x, d0); d1 = fmaf(fv.y, ev.y, d1);
                            d2 = fmaf(fv.z, ev.z, d2); d3 = fmaf(fv.w, ev.w, d3);
                        }
                        float s = fmaf(2.f, (d0 + d1) + (d2 + d3), -snorm[j]);
                        if (s > bw || (s == bw && j < wj)) { bw = s; wj = j; }
                    }
                }
                #pragma unroll
                for (int off = 16; off > 0; off >>= 1) {
                    float ob = __shfl_xor_sync(0xffffffffu, bw, off);
                    int   oj = __shfl_xor_sync(0xffffffffu, wj, off);
                    if (ob > bw || (ob == bw && oj < wj)) { bw = ob; wj = oj; }
                }
                if (lane == l) jwin[h] = wj;
            }
        }

        if (tig == 0) {
            swidx[wid * 16 + gid]     = jwin[0];
            swidx[wid * 16 + 8 + gid] = jwin[1];
        }
        __syncthreads();

        // ---- output gather (from smem fp32 codebook) + exact diff
        const float4* xin = (const float4*)(x + (size_t)t * TILE_M * DIM);
        float4* oq = (float4*)(out_q + (size_t)t * TILE_M * DIM);
        const float4* cb4 = (const float4*)cbf;   // row stride CBS/4 float4
        float td = 0.f;
        #pragma unroll
        for (int it = 0; it < (TILE_M * 16) / TPB; it++) {
            int i = tid + it * TPB;
            int row = i >> 4, v = i & 15;
            float4 e = cb4[swidx[row] * (CBS / 4) + v];
            float4 xv = xin[i];
            oq[i] = e;
            float d0 = e.x - xv.x, d1 = e.y - xv.y, d2 = e.z - xv.z, d3 = e.w - xv.w;
            td = fmaf(d0, d0, td); td = fmaf(d1, d1, td);
            td = fmaf(d2, d2, td); td = fmaf(d3, d3, td);
        }
        if (tid < TILE_M) out_idx[(size_t)t * TILE_M + tid] = (float)swidx[tid];

        #pragma unroll
        for (int off = 16; off > 0; off >>= 1)
            td += __shfl_down_sync(0xffffffffu, td, off);
        if (lane == 0) sred[wid] = td;
        __syncthreads();
        if (tid == 0) {
            float s = 0.f;
            #pragma unroll
            for (int w = 0; w < NWARP; w++) s += sred[w];
            blockdiff += s;                       // fixed tile order per block
        }
        __syncthreads();
    }

    // ---- fused deterministic finalize: last block sums per-block partials
    if (tid == 0) {
        g_partials[blockIdx.x] = blockdiff;
        __threadfence();
        unsigned int prev = atomicAdd(&g_done, 1u);
        if (prev == GRIDSZ - 1) {
            float s = 0.f;
            #pragma unroll 4
            for (int i = 0; i < GRIDSZ; i++) s += g_partials[i];   // fixed order
            *out_diff = s * (1.0f / (float)((size_t)NROWS * DIM));
            g_done = 0;                           // reset for next graph replay
            __threadfence();
        }
    }
}

extern "C" void kernel_launch(void* const* d_in, const int* in_sizes, int n_in,
                              void* d_out, int out_size)
{
    const float* x     = (const float*)d_in[0];
    const float* embed = (const float*)d_in[1];

    float* out      = (float*)d_out;
    float* out_q    = out;
    float* out_diff = out + (size_t)NROWS * DIM;
    float* out_idx  = out + (size_t)NROWS * DIM + 1;

    cudaFuncSetAttribute(vq_kernel, cudaFuncAttributeMaxDynamicSharedMemorySize, SMEM_TOTAL);

    vq_kernel<<<GRIDSZ, TPB, SMEM_TOTAL>>>(x, embed, out_q, out_idx, out_diff);
}